// round 3
// baseline (speedup 1.0000x reference)
#include <cuda_runtime.h>

// Problem constants (VisualPromptEncoder_49074296324730)
#define BB    8
#define CC    256
#define HH    160
#define WW    160
#define NN    100    // boxes per image
#define NCLS  80     // classes
#define TROWS 32     // tile rows
#define NTILE 5      // HH / TROWS
#define PSTR  161    // padded SMEM row stride (conflict-free scans)
#define CHUNK 16     // columns per thread in row scan
#define NCH   10     // WW / CHUNK
#define THR1  320    // NCH * TROWS

// Scratch: pooled per-box features, layout [B][N][C]
__device__ float g_pooled[BB * NN * CC];

// ---------------------------------------------------------------------------
// Kernel 1: per (b,c) plane — streaming tiled SAT with register row-scan.
// grid = B*C blocks, 320 threads. Smem touched only 3x per element.
// ---------------------------------------------------------------------------
__global__ void __launch_bounds__(THR1, 5)
sat_pool_kernel(const float* __restrict__ feat,
                const float* __restrict__ boxes,
                const int*   __restrict__ img_h,
                const int*   __restrict__ img_w)
{
    __shared__ float s[TROWS * PSTR];   // scanned rows / SAT rows
    __shared__ float carry[WW];         // running column sums across tiles
    __shared__ float cs[THR1];          // per-(row,chunk) sums, idx = k*32 + r
    __shared__ float cv[4 * NN];        // corner SAT values
    __shared__ int   cy[4 * NN];        // corner y (0..160)
    __shared__ int   cx[4 * NN];        // corner x (0..160)

    const int blk = blockIdx.x;         // b*CC + c
    const int b   = blk >> 8;
    const int c   = blk & 255;
    const int tid = threadIdx.x;        // 0..319
    const int r   = tid & 31;           // tile row
    const int k   = tid >> 5;           // column chunk 0..9

    // ---- setup ----
    if (tid < WW) carry[tid] = 0.f;
    if (tid < NN) {
        const float sx = (float)WW / (float)img_w[0];
        const float sy = (float)HH / (float)img_h[0];
        const float* bx = boxes + ((size_t)b * NN + tid) * 4;
        const int x1 = (int)fminf(fmaxf(floorf(bx[0] * sx), 0.f), (float)WW);
        const int y1 = (int)fminf(fmaxf(floorf(bx[1] * sy), 0.f), (float)HH);
        const int x2 = (int)fminf(fmaxf(floorf(bx[2] * sx), 0.f), (float)WW);
        const int y2 = (int)fminf(fmaxf(floorf(bx[3] * sy), 0.f), (float)HH);
        cy[tid          ] = y2; cx[tid          ] = x2;   // s22
        cy[tid +     NN ] = y1; cx[tid +     NN ] = x2;   // s12
        cy[tid + 2 * NN ] = y2; cx[tid + 2 * NN ] = x1;   // s21
        cy[tid + 3 * NN ] = y1; cx[tid + 3 * NN ] = x1;   // s11
    }
    #pragma unroll
    for (int j = tid; j < 4 * NN; j += THR1) cv[j] = 0.f;
    __syncthreads();

    const float* plane = feat + (size_t)blk * (HH * WW);

    for (int t = 0; t < NTILE; t++) {
        // ---- load chunk directly to registers: row (32t+r), cols 16k..16k+15 ----
        float v[CHUNK];
        {
            const float4* rp = (const float4*)(plane + (size_t)(t * TROWS + r) * WW + k * CHUNK);
            const float4 a0 = rp[0], a1 = rp[1], a2 = rp[2], a3 = rp[3];
            v[0]=a0.x; v[1]=a0.y; v[2]=a0.z; v[3]=a0.w;
            v[4]=a1.x; v[5]=a1.y; v[6]=a1.z; v[7]=a1.w;
            v[8]=a2.x; v[9]=a2.y; v[10]=a2.z; v[11]=a2.w;
            v[12]=a3.x; v[13]=a3.y; v[14]=a3.z; v[15]=a3.w;
        }
        float csum = 0.f;
        #pragma unroll
        for (int i = 0; i < CHUNK; i++) csum += v[i];
        cs[tid] = csum;                  // tid == k*32 + r
        __syncthreads();

        // ---- row scan in registers with chunk offset; single smem write ----
        {
            float run = 0.f;
            #pragma unroll
            for (int j = 0; j < NCH - 1; j++)
                run += (j < k) ? cs[j * 32 + r] : 0.f;
            float* d = &s[r * PSTR + k * CHUNK];
            #pragma unroll
            for (int i = 0; i < CHUNK; i++) {
                run += v[i];
                d[i] = run;
            }
        }
        __syncthreads();

        // ---- column scan + carry: threads 0..159 own a column each ----
        if (tid < WW) {
            float run = carry[tid];
            #pragma unroll
            for (int ry = 0; ry < TROWS; ry++) {
                const int idx = ry * PSTR + tid;
                run += s[idx];
                s[idx] = run;            // SAT rows [32t .. 32t+31]
            }
            carry[tid] = run;
        }
        __syncthreads();

        // ---- corner harvest ----
        #pragma unroll
        for (int j = tid; j < 4 * NN; j += THR1) {
            const int y = cy[j];
            if (((y - 1) >> 5) == t && cx[j] >= 1)
                cv[j] = s[(y - 1 - t * TROWS) * PSTR + (cx[j] - 1)];
        }
        __syncthreads();
    }

    // ---- finalize boxes ----
    if (tid < NN) {
        const int x2 = cx[tid], y2 = cy[tid];
        const int x1 = cx[tid + 2 * NN], y1 = cy[tid + NN];
        float out = 0.f;
        if (x2 > x1 && y2 > y1) {
            const float sum = cv[tid] - cv[tid + NN] - cv[tid + 2 * NN] + cv[tid + 3 * NN];
            int area = (x2 - x1) * (y2 - y1);
            if (area < 1) area = 1;
            out = sum / (float)area;
        }
        g_pooled[((size_t)b * NN + tid) * CC + c] = out;
    }
}

// ---------------------------------------------------------------------------
// Kernel 2: segment mean per (b, cls) via deterministic ballot compaction
// grid = B*NCLS blocks, 256 threads (one per channel)
// ---------------------------------------------------------------------------
__global__ void __launch_bounds__(256)
reduce_kernel(const float* __restrict__ feat,
              const float* __restrict__ boxes,
              const int*   __restrict__ gtc,
              const int*   __restrict__ neg_y,
              const int*   __restrict__ neg_x,
              const int*   __restrict__ img_h,
              const int*   __restrict__ img_w,
              float*       __restrict__ out)
{
    const int blk = blockIdx.x;               // b*NCLS + cls
    const int b   = blk / NCLS;
    const int cls = blk - b * NCLS;
    const int c   = threadIdx.x;              // 0..255
    const int w   = c >> 5;
    const int lane = c & 31;

    __shared__ int s_idx[NN];
    __shared__ int s_wcnt[8];

    // match flag: valid box of this class, computed by threads c < NN
    bool match = false;
    if (c < NN) {
        const int cl = gtc[b * NN + c];
        const float sx = (float)WW / (float)img_w[0];
        const float sy = (float)HH / (float)img_h[0];
        const float* bx = boxes + ((size_t)b * NN + c) * 4;
        const int x1 = (int)fminf(fmaxf(floorf(bx[0] * sx), 0.f), (float)WW);
        const int y1 = (int)fminf(fmaxf(floorf(bx[1] * sy), 0.f), (float)HH);
        const int x2 = (int)fminf(fmaxf(floorf(bx[2] * sx), 0.f), (float)WW);
        const int y2 = (int)fminf(fmaxf(floorf(bx[3] * sy), 0.f), (float)HH);
        match = (cl == cls) && (x2 > x1) && (y2 > y1);
    }
    const unsigned m = __ballot_sync(0xffffffffu, match);
    if (lane == 0) s_wcnt[w] = __popc(m);
    __syncthreads();

    int woff = 0, total = 0;
    #pragma unroll
    for (int j = 0; j < 8; j++) {
        const int wc = s_wcnt[j];
        woff  += (j < w) ? wc : 0;
        total += wc;
    }
    if (match)
        s_idx[woff + __popc(m & ((1u << lane) - 1u))] = c;
    __syncthreads();

    float r;
    if (total > 0) {
        const float* pooled_b = g_pooled + (size_t)b * NN * CC;
        float sum = 0.f;
        for (int i = 0; i < total; i++)
            sum += pooled_b[(size_t)s_idx[i] * CC + c];
        r = sum / (float)total;
    } else {
        const int ny = neg_y[b * NCLS + cls];
        const int nx = neg_x[b * NCLS + cls];
        r = feat[(((size_t)b * CC + c) * HH + ny) * WW + nx];
    }
    out[(size_t)blk * CC + c] = r;
}

// ---------------------------------------------------------------------------
extern "C" void kernel_launch(void* const* d_in, const int* in_sizes, int n_in,
                              void* d_out, int out_size)
{
    const float* feat  = (const float*)d_in[0];   // [8,256,160,160] f32
    const float* boxes = (const float*)d_in[1];   // [8,100,4] f32
    const int*   gtc   = (const int*)d_in[2];     // [8,100] i32
    const int*   ngy   = (const int*)d_in[3];     // [8,80] i32
    const int*   ngx   = (const int*)d_in[4];     // [8,80] i32
    const int*   ih    = (const int*)d_in[5];     // scalar
    const int*   iw    = (const int*)d_in[6];     // scalar
    float*       out   = (float*)d_out;           // [8,80,256] f32

    sat_pool_kernel<<<BB * CC, THR1>>>(feat, boxes, ih, iw);
    reduce_kernel<<<BB * NCLS, 256>>>(feat, boxes, gtc, ngy, ngx, ih, iw, out);
}

// round 4
// speedup vs baseline: 1.3743x; 1.3743x over previous
#include <cuda_runtime.h>

// Problem constants (VisualPromptEncoder_49074296324730)
#define BB    8
#define CC    256
#define HH    160
#define WW    160
#define NN    100    // boxes per image
#define NCLS  80     // classes
#define TROWS 32     // tile rows
#define NTILE 5      // HH / TROWS
#define PSTR  164    // padded row stride (mult of 4 for float4, conflict-free)
#define THR1  256    // 8 warps

// ---------------------------------------------------------------------------
// Single fused kernel: per (b,c) plane — streaming tiled SAT, box pooling,
// and per-class scatter-mean with negative fallback, all in one block.
// grid = B*C = 2048 blocks, 256 threads, ~28KB smem -> 8 blocks/SM
// ---------------------------------------------------------------------------
__global__ void __launch_bounds__(THR1, 8)
vpe_fused_kernel(const float* __restrict__ feat,
                 const float* __restrict__ boxes,
                 const int*   __restrict__ gtc,
                 const int*   __restrict__ neg_y,
                 const int*   __restrict__ neg_x,
                 const int*   __restrict__ img_h,
                 const int*   __restrict__ img_w,
                 float*       __restrict__ out)
{
    __shared__ float s[TROWS * PSTR];   // staged tile -> scanned rows -> SAT rows
    __shared__ float carry[WW];         // running column sums across tiles
    __shared__ float cv[4 * NN];        // corner SAT values
    __shared__ short cy[4 * NN];        // corner y (0..160)
    __shared__ short cx[4 * NN];        // corner x (0..160)
    __shared__ float s_pool[NN];        // pooled value per box (this channel)
    __shared__ int   s_cls[NN];         // class per box (-1 if invalid)

    const int blk  = blockIdx.x;        // b*CC + c
    const int b    = blk >> 8;
    const int c    = blk & 255;
    const int tid  = threadIdx.x;       // 0..255
    const int w    = tid >> 5;          // warp 0..7
    const int lane = tid & 31;

    // ---- setup: box corners, classes ----
    if (tid < WW) carry[tid] = 0.f;
    if (tid < NN) {
        const float sx = (float)WW / (float)img_w[0];
        const float sy = (float)HH / (float)img_h[0];
        const float* bx = boxes + ((size_t)b * NN + tid) * 4;
        const int x1 = (int)fminf(fmaxf(floorf(bx[0] * sx), 0.f), (float)WW);
        const int y1 = (int)fminf(fmaxf(floorf(bx[1] * sy), 0.f), (float)HH);
        const int x2 = (int)fminf(fmaxf(floorf(bx[2] * sx), 0.f), (float)WW);
        const int y2 = (int)fminf(fmaxf(floorf(bx[3] * sy), 0.f), (float)HH);
        cy[tid          ] = (short)y2; cx[tid          ] = (short)x2;  // s22
        cy[tid +     NN ] = (short)y1; cx[tid +     NN ] = (short)x2;  // s12
        cy[tid + 2 * NN ] = (short)y2; cx[tid + 2 * NN ] = (short)x1;  // s21
        cy[tid + 3 * NN ] = (short)y1; cx[tid + 3 * NN ] = (short)x1;  // s11
        const bool valid = (x2 > x1) && (y2 > y1);
        s_cls[tid] = valid ? gtc[b * NN + tid] : -1;
    }
    #pragma unroll
    for (int j = tid; j < 4 * NN; j += THR1) cv[j] = 0.f;
    __syncthreads();

    const float4* plane4 = (const float4*)(feat + (size_t)blk * (HH * WW));

    for (int t = 0; t < NTILE; t++) {
        // ---- coalesced staging: 1280 float4, 5 per thread ----
        const float4* tp = plane4 + t * (TROWS * WW / 4);
        #pragma unroll
        for (int it = 0; it < 5; it++) {
            const int j  = it * THR1 + tid;    // float4 index within tile
            const int ry = j / 40;
            const int x4 = j - ry * 40;
            *(float4*)&s[ry * PSTR + x4 * 4] = tp[j];
        }
        __syncthreads();

        // ---- row scan: warp per row (4 rows per warp), lane owns 5 contiguous ----
        #pragma unroll
        for (int q = 0; q < 4; q++) {
            const int r = w + 8 * q;           // row within tile
            float* p = &s[r * PSTR + lane * 5];
            float v0 = p[0], v1 = p[1], v2 = p[2], v3 = p[3], v4 = p[4];
            v1 += v0; v2 += v1; v3 += v2; v4 += v3;   // serial inclusive prefix
            // inclusive warp scan of lane totals
            float sc = v4;
            #pragma unroll
            for (int d = 1; d < 32; d <<= 1) {
                const float o = __shfl_up_sync(0xffffffffu, sc, d);
                if (lane >= d) sc += o;
            }
            const float excl = sc - v4;
            p[0] = v0 + excl; p[1] = v1 + excl; p[2] = v2 + excl;
            p[3] = v3 + excl; p[4] = v4 + excl;
        }
        __syncthreads();

        // ---- column scan + carry: threads 0..159 own a column each ----
        if (tid < WW) {
            float run = carry[tid];
            #pragma unroll
            for (int ry = 0; ry < TROWS; ry++) {
                const int idx = ry * PSTR + tid;
                run += s[idx];
                s[idx] = run;                 // SAT rows [32t .. 32t+31]
            }
            carry[tid] = run;
        }
        __syncthreads();

        // ---- corner harvest: SAT(y,x) for corners with y-1 in this tile ----
        #pragma unroll
        for (int j = tid; j < 4 * NN; j += THR1) {
            const int y = cy[j];
            if (((y - 1) >> 5) == t && cx[j] >= 1)
                cv[j] = s[(y - 1 - t * TROWS) * PSTR + (cx[j] - 1)];
        }
        __syncthreads();
    }

    // ---- pooled value per box ----
    if (tid < NN) {
        const int x2 = cx[tid], y2 = cy[tid];
        const int x1 = cx[tid + 2 * NN], y1 = cy[tid + NN];
        float pv = 0.f;
        if (x2 > x1 && y2 > y1) {
            const float sum = cv[tid] - cv[tid + NN] - cv[tid + 2 * NN] + cv[tid + 3 * NN];
            int area = (x2 - x1) * (y2 - y1);
            if (area < 1) area = 1;
            pv = sum / (float)area;
        }
        s_pool[tid] = pv;
    }
    __syncthreads();

    // ---- per-class mean + negative fallback, write out[b, cls, c] ----
    if (tid < NCLS) {
        const int cls = tid;
        float sum = 0.f;
        int   cnt = 0;
        #pragma unroll 4
        for (int n = 0; n < NN; n++) {
            if (s_cls[n] == cls) { sum += s_pool[n]; cnt++; }
        }
        float r;
        if (cnt > 0) {
            r = sum / (float)cnt;
        } else {
            const int ny = neg_y[b * NCLS + cls];
            const int nx = neg_x[b * NCLS + cls];
            r = feat[(((size_t)b * CC + c) * HH + ny) * WW + nx];
        }
        out[((size_t)b * NCLS + cls) * CC + c] = r;
    }
}

// ---------------------------------------------------------------------------
extern "C" void kernel_launch(void* const* d_in, const int* in_sizes, int n_in,
                              void* d_out, int out_size)
{
    const float* feat  = (const float*)d_in[0];   // [8,256,160,160] f32
    const float* boxes = (const float*)d_in[1];   // [8,100,4] f32
    const int*   gtc   = (const int*)d_in[2];     // [8,100] i32
    const int*   ngy   = (const int*)d_in[3];     // [8,80] i32
    const int*   ngx   = (const int*)d_in[4];     // [8,80] i32
    const int*   ih    = (const int*)d_in[5];     // scalar
    const int*   iw    = (const int*)d_in[6];     // scalar
    float*       out   = (float*)d_out;           // [8,80,256] f32

    vpe_fused_kernel<<<BB * CC, THR1>>>(feat, boxes, gtc, ngy, ngx, ih, iw, out);
}

// round 5
// speedup vs baseline: 1.4065x; 1.0234x over previous
#include <cuda_runtime.h>

// Problem constants (VisualPromptEncoder_49074296324730)
#define BB    8
#define CC    256
#define HH    160
#define WW    160
#define NN    100    // boxes per image
#define NCLS  80     // classes
#define TROWS 32     // tile rows
#define NTILE 5      // HH / TROWS
#define PSTR  164    // padded row stride (mult of 4 for float4, conflict-free)
#define THR1  256    // 8 warps

// ---------------------------------------------------------------------------
// Single fused kernel: per (b,c) plane — streaming tiled SAT, box pooling,
// and per-class scatter-mean with negative fallback, all in one block.
// Row scan is done in registers straight from coalesced LDG (no smem staging).
// grid = B*C = 2048 blocks, 256 threads, ~28KB smem
// ---------------------------------------------------------------------------
__global__ void __launch_bounds__(THR1, 6)
vpe_fused_kernel(const float* __restrict__ feat,
                 const float* __restrict__ boxes,
                 const int*   __restrict__ gtc,
                 const int*   __restrict__ neg_y,
                 const int*   __restrict__ neg_x,
                 const int*   __restrict__ img_h,
                 const int*   __restrict__ img_w,
                 float*       __restrict__ out)
{
    __shared__ float s[TROWS * PSTR];   // scanned rows -> SAT rows
    __shared__ float carry[WW];         // running column sums across tiles
    __shared__ float cv[4 * NN];        // corner SAT values
    __shared__ short cy[4 * NN];        // corner y (0..160)
    __shared__ short cx[4 * NN];        // corner x (0..160)
    __shared__ float s_pool[NN];        // pooled value per box (this channel)
    __shared__ int   s_cls[NN];         // class per box (-1 if invalid)

    const int blk  = blockIdx.x;        // b*CC + c
    const int b    = blk >> 8;
    const int c    = blk & 255;
    const int tid  = threadIdx.x;       // 0..255
    const int w    = tid >> 5;          // warp 0..7
    const int lane = tid & 31;

    // ---- setup: box corners, classes ----
    if (tid < WW) carry[tid] = 0.f;
    if (tid < NN) {
        const float sx = (float)WW / (float)img_w[0];
        const float sy = (float)HH / (float)img_h[0];
        const float* bx = boxes + ((size_t)b * NN + tid) * 4;
        const int x1 = (int)fminf(fmaxf(floorf(bx[0] * sx), 0.f), (float)WW);
        const int y1 = (int)fminf(fmaxf(floorf(bx[1] * sy), 0.f), (float)HH);
        const int x2 = (int)fminf(fmaxf(floorf(bx[2] * sx), 0.f), (float)WW);
        const int y2 = (int)fminf(fmaxf(floorf(bx[3] * sy), 0.f), (float)HH);
        cy[tid          ] = (short)y2; cx[tid          ] = (short)x2;  // s22
        cy[tid +     NN ] = (short)y1; cx[tid +     NN ] = (short)x2;  // s12
        cy[tid + 2 * NN ] = (short)y2; cx[tid + 2 * NN ] = (short)x1;  // s21
        cy[tid + 3 * NN ] = (short)y1; cx[tid + 3 * NN ] = (short)x1;  // s11
        const bool valid = (x2 > x1) && (y2 > y1);
        s_cls[tid] = valid ? gtc[b * NN + tid] : -1;
    }
    #pragma unroll
    for (int j = tid; j < 4 * NN; j += THR1) cv[j] = 0.f;
    __syncthreads();

    const float4* plane4 = (const float4*)(feat + (size_t)blk * (HH * WW));

    for (int t = 0; t < NTILE; t++) {
        // ---- row scan in registers: warp w handles rows w, w+8, w+16, w+24 ----
        #pragma unroll
        for (int q = 0; q < 4; q++) {
            const int r = w + 8 * q;                      // row within tile
            const float4* row4 = plane4 + (size_t)(t * TROWS + r) * 40;

            // coalesced load: lane -> chunk `lane` (cols 4L..4L+3);
            // lanes 0..7 also own chunk 32+lane (cols 128+4L..131+4L)
            float4 a = row4[lane];
            float4 bb2;
            if (lane < 8) bb2 = row4[32 + lane];
            else          bb2 = make_float4(0.f, 0.f, 0.f, 0.f);

            // prefix inside chunks
            a.y += a.x; a.z += a.y; a.w += a.z;
            bb2.y += bb2.x; bb2.z += bb2.y; bb2.w += bb2.z;
            const float ta = a.w;
            const float tb = bb2.w;

            // warp inclusive scan of first-32 chunk totals
            float ia = ta;
            #pragma unroll
            for (int d = 1; d < 32; d <<= 1) {
                const float o = __shfl_up_sync(0xffffffffu, ia, d);
                if (lane >= d) ia += o;
            }
            const float ea = ia - ta;                    // exclusive offset, chunk lane
            const float T0 = __shfl_sync(0xffffffffu, ia, 31);  // total cols 0..127

            // inclusive scan of the 8 tail-chunk totals (lanes 0..7)
            float ib = tb;
            #pragma unroll
            for (int d = 1; d < 8; d <<= 1) {
                const float o = __shfl_up_sync(0xffffffffu, ib, d);
                if (lane >= d) ib += o;
            }
            const float eb = T0 + (ib - tb);             // exclusive offset, chunk 32+lane

            // single smem write of the scanned row
            float* dst = &s[r * PSTR];
            *(float4*)&dst[4 * lane] =
                make_float4(a.x + ea, a.y + ea, a.z + ea, a.w + ea);
            if (lane < 8)
                *(float4*)&dst[128 + 4 * lane] =
                    make_float4(bb2.x + eb, bb2.y + eb, bb2.z + eb, bb2.w + eb);
        }
        __syncthreads();

        // ---- column scan + carry: threads 0..159 own a column each ----
        if (tid < WW) {
            float run = carry[tid];
            #pragma unroll
            for (int ry = 0; ry < TROWS; ry++) {
                const int idx = ry * PSTR + tid;
                run += s[idx];
                s[idx] = run;                 // SAT rows [32t .. 32t+31]
            }
            carry[tid] = run;
        }
        __syncthreads();

        // ---- corner harvest: SAT(y,x) for corners with y-1 in this tile ----
        #pragma unroll
        for (int j = tid; j < 4 * NN; j += THR1) {
            const int y = cy[j];
            if (((y - 1) >> 5) == t && cx[j] >= 1)
                cv[j] = s[(y - 1 - t * TROWS) * PSTR + (cx[j] - 1)];
        }
        __syncthreads();
    }

    // ---- pooled value per box ----
    if (tid < NN) {
        const int x2 = cx[tid], y2 = cy[tid];
        const int x1 = cx[tid + 2 * NN], y1 = cy[tid + NN];
        float pv = 0.f;
        if (x2 > x1 && y2 > y1) {
            const float sum = cv[tid] - cv[tid + NN] - cv[tid + 2 * NN] + cv[tid + 3 * NN];
            int area = (x2 - x1) * (y2 - y1);
            if (area < 1) area = 1;
            pv = sum / (float)area;
        }
        s_pool[tid] = pv;
    }
    __syncthreads();

    // ---- per-class mean + negative fallback, write out[b, cls, c] ----
    if (tid < NCLS) {
        const int cls = tid;
        float sum = 0.f;
        int   cnt = 0;
        #pragma unroll 4
        for (int n = 0; n < NN; n++) {
            if (s_cls[n] == cls) { sum += s_pool[n]; cnt++; }
        }
        float r;
        if (cnt > 0) {
            r = sum / (float)cnt;
        } else {
            const int ny = neg_y[b * NCLS + cls];
            const int nx = neg_x[b * NCLS + cls];
            r = feat[(((size_t)b * CC + c) * HH + ny) * WW + nx];
        }
        out[((size_t)b * NCLS + cls) * CC + c] = r;
    }
}

// ---------------------------------------------------------------------------
extern "C" void kernel_launch(void* const* d_in, const int* in_sizes, int n_in,
                              void* d_out, int out_size)
{
    const float* feat  = (const float*)d_in[0];   // [8,256,160,160] f32
    const float* boxes = (const float*)d_in[1];   // [8,100,4] f32
    const int*   gtc   = (const int*)d_in[2];     // [8,100] i32
    const int*   ngy   = (const int*)d_in[3];     // [8,80] i32
    const int*   ngx   = (const int*)d_in[4];     // [8,80] i32
    const int*   ih    = (const int*)d_in[5];     // scalar
    const int*   iw    = (const int*)d_in[6];     // scalar
    float*       out   = (float*)d_out;           // [8,80,256] f32

    vpe_fused_kernel<<<BB * CC, THR1>>>(feat, boxes, gtc, ngy, ngx, ih, iw, out);
}